// round 15
// baseline (speedup 1.0000x reference)
#include <cuda_runtime.h>
#include <cuda_fp16.h>
#include <cstdint>

#define DD    128
#define BD    16384
#define SQ36  0.28867513459481287f

// ---- smem: two ping/pong tile-sets + consumer scratch (1 CTA/SM) ----
#define BUF(k)   ((k) * 65536)       // fp16 S tile (32KB) at +0
#define WOFF     32768               // fp16 W tile (32KB); becomes fp16 comm after MMA
#define V0OFF    131072              // v ping [128] fp32
#define V1OFF    131584              // v pong [128] fp32
#define YS(k)    (132096 + (k) * 512)  // y0 stage per buffer
#define SMEM_REQ 133120

#define BAR_SYNC(id, cnt)   asm volatile("bar.sync %0, %1;"   :: "r"(id), "r"(cnt) : "memory")
#define BAR_ARRIVE(id, cnt) asm volatile("bar.arrive %0, %1;" :: "r"(id), "r"(cnt) : "memory")
#define MEMBAR_CTA()        asm volatile("membar.cta;" ::: "memory")

__device__ __forceinline__ uint32_t smem_u32(const void* p) {
    uint32_t a;
    asm("{ .reg .u64 t; cvta.to.shared.u64 t, %1; cvt.u32.u64 %0, t; }" : "=r"(a) : "l"(p));
    return a;
}
__device__ __forceinline__ void ldsm_x4(uint32_t* r, uint32_t addr) {
    asm volatile("ldmatrix.sync.aligned.m8n8.x4.shared.b16 {%0,%1,%2,%3}, [%4];"
                 : "=r"(r[0]), "=r"(r[1]), "=r"(r[2]), "=r"(r[3]) : "r"(addr));
}
__device__ __forceinline__ void ldsm_x4t(uint32_t* r, uint32_t addr) {
    asm volatile("ldmatrix.sync.aligned.m8n8.x4.trans.shared.b16 {%0,%1,%2,%3}, [%4];"
                 : "=r"(r[0]), "=r"(r[1]), "=r"(r[2]), "=r"(r[3]) : "r"(addr));
}
// fp16 in, fp16 accum (d packed f16x2: d[0]=row lr, d[1]=row lr+8)
__device__ __forceinline__ void mma16816h(uint32_t* d, const uint32_t* a, const uint32_t* b) {
    asm volatile("mma.sync.aligned.m16n8k16.row.col.f16.f16.f16.f16 "
                 "{%0,%1}, {%2,%3,%4,%5}, {%6,%7}, {%0,%1};"
                 : "+r"(d[0]), "+r"(d[1])
                 : "r"(a[0]), "r"(a[1]), "r"(a[2]), "r"(a[3]), "r"(b[0]), "r"(b[1]));
}
// fp16 tile address: pitch 256B/row (16 chunks of 16B = 8 cols), chunk ^= row&7
__device__ __forceinline__ uint32_t taddr(uint32_t base, int row, int col) {
    int chunk = (col >> 3) ^ (row & 7);
    return base + row * 256 + (chunk << 4);
}
__device__ __forceinline__ uint32_t h2u(__half2 v) { return *reinterpret_cast<uint32_t*>(&v); }

__global__ __launch_bounds__(512, 1)
void magnus_kernel(const float* __restrict__ t0, const float* __restrict__ hp,
                   const float* __restrict__ y0,
                   const float* __restrict__ A0, const float* __restrict__ Wm,
                   float* __restrict__ out, int B)
{
    extern __shared__ char sm[];
    const uint32_t sb = smem_u32(sm);

    const int tid  = threadIdx.x;
    const int wid  = tid >> 5;
    const int step = gridDim.x;
    const int b0   = blockIdx.x;

    const float h   = hp[0];
    const float h2  = 0.5f * h;
    const float c24 = h * h * h * (1.0f / 24.0f);

    if (wid < 8) {
        // ================= PRODUCER (warps 0-7, 256 threads) =================
        const int ptid = tid;
        int i = 0;
        for (int bp = b0; bp < B; bp += step, ++i) {
            const int k = i & 1;
            if (i >= 2) BAR_SYNC(3 + k, 512);        // wait: buffer k free

            const float t0b = t0[bp];
            const float t1  = t0b + (0.5f - SQ36) * h;
            const float t2  = t0b + (0.5f + SQ36) * h;

            const float4* A0g = (const float4*)(A0 + (size_t)bp * BD);
            const float4* Wg  = (const float4*)(Wm + (size_t)bp * BD);
            float4* o1 = (float4*)(out + (size_t)B * DD + (size_t)bp * BD);
            float4* o2 = (float4*)(out + (size_t)B * DD + (size_t)B * BD + (size_t)bp * BD);

            float yv0 = 0.0f;
            if (ptid < DD) yv0 = y0[(size_t)bp * DD + ptid];   // hides behind stream

            // double-buffered pairs: 8 iterations, 8 floats (2 float4) per matrix each
            float4 pa[2][2], pw[2][2];
            {
                int f4 = 2 * ptid;
                pa[0][0] = A0g[f4]; pa[0][1] = A0g[f4 + 1];
                pw[0][0] = Wg[f4];  pw[0][1] = Wg[f4 + 1];
            }
            #pragma unroll
            for (int it = 0; it < 8; ++it) {
                const int cur = it & 1;
                if (it < 7) {
                    int f4 = 2 * (ptid + 256 * (it + 1));
                    pa[cur ^ 1][0] = A0g[f4]; pa[cur ^ 1][1] = A0g[f4 + 1];
                    pw[cur ^ 1][0] = Wg[f4];  pw[cur ^ 1][1] = Wg[f4 + 1];
                }
                const int p    = ptid + 256 * it;    // pair index (16B fp16 chunk)
                const int row  = p >> 4;
                const int cidx = p & 15;
                const int f4   = 2 * p;

                uint4 pS, pW;
                #pragma unroll
                for (int u = 0; u < 2; ++u) {
                    float4 a = pa[cur][u];
                    float4 w = pw[cur][u];
                    float4 x1, x2;
                    x1.x = fmaf(t1, w.x, a.x); x1.y = fmaf(t1, w.y, a.y);
                    x1.z = fmaf(t1, w.z, a.z); x1.w = fmaf(t1, w.w, a.w);
                    x2.x = fmaf(t2, w.x, a.x); x2.y = fmaf(t2, w.y, a.y);
                    x2.z = fmaf(t2, w.z, a.z); x2.w = fmaf(t2, w.w, a.w);
                    o1[f4 + u] = x1;
                    o2[f4 + u] = x2;
                    uint32_t s0 = h2u(__floats2half2_rn(x1.x + x2.x, x1.y + x2.y));
                    uint32_t s1 = h2u(__floats2half2_rn(x1.z + x2.z, x1.w + x2.w));
                    uint32_t w0 = h2u(__floats2half2_rn(w.x, w.y));
                    uint32_t w1 = h2u(__floats2half2_rn(w.z, w.w));
                    if (u == 0) { pS.x = s0; pS.y = s1; pW.x = w0; pW.y = w1; }
                    else        { pS.z = s0; pS.w = s1; pW.z = w0; pW.w = w1; }
                }
                uint32_t toff = (uint32_t)(row * 256 + ((cidx ^ (row & 7)) << 4));
                *(uint4*)(sm + BUF(k) + toff)        = pS;
                *(uint4*)(sm + BUF(k) + WOFF + toff) = pW;
            }
            if (ptid < DD) *(float*)(sm + YS(k) + ptid * 4) = yv0;
            MEMBAR_CTA();
            BAR_ARRIVE(1 + k, 512);                  // signal: buffer k full
        }
    } else {
        // ================= CONSUMER (warps 8-15, 256 threads) =================
        const int ctid  = tid - 256;
        const int clane = ctid & 31;
        const int cwid  = ctid >> 5;
        float* v0 = (float*)(sm + V0OFF);
        float* v1 = (float*)(sm + V1OFF);

        const int m0 = (cwid >> 2) << 6;   // 0 or 64
        const int n0 = (cwid & 3) << 5;    // 0,32,64,96
        const int arow = clane & 15;
        const int acol = (clane >> 4) << 3;
        const int r    = ctid >> 1;
        const int half = ctid & 1;

        int i = 0;
        for (int bc = b0; bc < B; bc += step, ++i) {
            const int k = i & 1;
            BAR_SYNC(1 + k, 512);                    // wait: buffer k full
            if (ctid < DD) v0[ctid] = *(const float*)(sm + YS(k) + ctid * 4);

            const uint32_t aS = sb + BUF(k);
            const uint32_t aW = aS + WOFF;

            // ---- MMA: CM = S@W + (-W)@S (= [S,W]); 2x4 warp grid, 64x32/warp ----
            uint32_t acc[4][4][2];
            #pragma unroll
            for (int mh = 0; mh < 4; ++mh)
                #pragma unroll
                for (int nt = 0; nt < 4; ++nt) { acc[mh][nt][0] = 0u; acc[mh][nt][1] = 0u; }

            #pragma unroll
            for (int k0 = 0; k0 < DD; k0 += 16) {
                uint32_t fs[4][4], fw[4][4];
                #pragma unroll
                for (int mh = 0; mh < 4; ++mh) {
                    ldsm_x4(fs[mh], taddr(aS, m0 + 16 * mh + arow, k0 + acol));
                    ldsm_x4(fw[mh], taddr(aW, m0 + 16 * mh + arow, k0 + acol));
                    #pragma unroll
                    for (int qq = 0; qq < 4; ++qq) fw[mh][qq] ^= 0x80008000u;   // -W
                }
                #pragma unroll
                for (int nn = 0; nn < 2; ++nn) {
                    uint32_t bW[4], bS[4];
                    ldsm_x4t(bW, taddr(aW, k0 + arow, n0 + 16 * nn + acol));
                    ldsm_x4t(bS, taddr(aS, k0 + arow, n0 + 16 * nn + acol));
                    #pragma unroll
                    for (int mh = 0; mh < 4; ++mh) {
                        mma16816h(acc[mh][2 * nn],     fs[mh], bW);
                        mma16816h(acc[mh][2 * nn + 1], fs[mh], bW + 2);
                        mma16816h(acc[mh][2 * nn],     fw[mh], bS);
                        mma16816h(acc[mh][2 * nn + 1], fw[mh], bS + 2);
                    }
                }
            }
            BAR_SYNC(5, 256);    // all consumer ldsm of W tile done -> reusable

            // ---- store fp16 CM into W-tile region ----
            {
                const int lr = clane >> 2;
                const int lc = (clane & 3) << 1;
                #pragma unroll
                for (int mh = 0; mh < 4; ++mh)
                    #pragma unroll
                    for (int nt = 0; nt < 4; ++nt)
                        #pragma unroll
                        for (int hf = 0; hf < 2; ++hf) {
                            int row = m0 + 16 * mh + lr + 8 * hf;
                            int col = n0 + 8 * nt + lc;
                            uint32_t addr = (uint32_t)(row * 256 + (((col >> 3) ^ (row & 7)) << 4) + ((col & 7) << 1));
                            *(uint32_t*)(sm + BUF(k) + WOFF + addr) = acc[mh][nt][hf];
                        }
            }
            BAR_SYNC(5, 256);

            // ---- om[64] = h/2 * S - c24 * CM  (row r, half) ----
            float om[64];
            #pragma unroll
            for (int j = 0; j < 8; ++j) {
                uint32_t cc = (uint32_t)(r * 256 + ((8 * half + (j ^ (r & 7))) << 4));
                uint4 us = *(const uint4*)(sm + BUF(k) + cc);
                uint4 uc = *(const uint4*)(sm + BUF(k) + WOFF + cc);
                const uint32_t ss[4] = {us.x, us.y, us.z, us.w};
                const uint32_t cs[4] = {uc.x, uc.y, uc.z, uc.w};
                int jb = j * 8;
                #pragma unroll
                for (int t = 0; t < 4; ++t) {
                    float2 fs2 = __half22float2(*(const __half2*)&ss[t]);
                    float2 fc2 = __half22float2(*(const __half2*)&cs[t]);
                    om[jb + 2 * t + 0] = fmaf(h2, fs2.x, -c24 * fc2.x);
                    om[jb + 2 * t + 1] = fmaf(h2, fs2.y, -c24 * fc2.y);
                }
            }
            BAR_ARRIVE(3 + k, 512);                  // signal: buffer k free
            BAR_SYNC(5, 256);                        // v0 init visible to all consumers

            // ---- Taylor: y = expm(Omega) @ y0, 7 terms, shfl pair-reduce ----
            float yvreg = v0[r];
            #pragma unroll
            for (int kk = 1; kk <= 7; ++kk) {
                const float* vcur = (kk & 1) ? v0 : v1;
                float*       vnxt = (kk & 1) ? v1 : v0;
                const float4* vv = (const float4*)(vcur + 64 * half);
                float s0 = 0.f, s1 = 0.f, s2 = 0.f, s3 = 0.f;
                #pragma unroll
                for (int f4 = 0; f4 < 16; ++f4) {
                    float4 f = vv[f4];
                    s0 = fmaf(om[4 * f4 + 0], f.x, s0);
                    s1 = fmaf(om[4 * f4 + 1], f.y, s1);
                    s2 = fmaf(om[4 * f4 + 2], f.z, s2);
                    s3 = fmaf(om[4 * f4 + 3], f.w, s3);
                }
                float tot = (s0 + s1) + (s2 + s3);
                tot += __shfl_xor_sync(0xffffffffu, tot, 1);
                float nv = tot * (1.0f / (float)kk);
                yvreg += nv;
                if (half == 0) vnxt[r] = nv;
                BAR_SYNC(5, 256);
            }
            if (half == 0) out[(size_t)bc * DD + r] = yvreg;
        }
    }
}

extern "C" void kernel_launch(void* const* d_in, const int* in_sizes, int n_in,
                              void* d_out, int out_size) {
    const float* t0 = (const float*)d_in[0];
    const float* h  = (const float*)d_in[1];
    const float* y0 = (const float*)d_in[2];
    const float* A0 = (const float*)d_in[3];
    const float* W  = (const float*)d_in[4];
    const int B = in_sizes[0];

    int grid = B < 152 ? B : 152;
    cudaFuncSetAttribute(magnus_kernel, cudaFuncAttributeMaxDynamicSharedMemorySize, SMEM_REQ);
    magnus_kernel<<<grid, 512, SMEM_REQ>>>(t0, h, y0, A0, W, (float*)d_out, B);
}

// round 16
// speedup vs baseline: 1.2936x; 1.2936x over previous
#include <cuda_runtime.h>
#include <cuda_fp16.h>
#include <cstdint>

#define DD    128
#define BD    16384
#define SQ36  0.28867513459481287f

// ---- smem: two ping/pong tile-sets + consumer scratch (1 CTA/SM) ----
#define BUF(k)   ((k) * 65536)       // fp16 S tile (32KB) at +0
#define WOFF     32768               // fp16 W tile (32KB); becomes fp16 comm after MMA
#define V0OFF    131072              // v ping [128] fp32
#define V1OFF    131584              // v pong [128] fp32
#define YS(k)    (132096 + (k) * 512)  // y0 stage per buffer
#define SMEM_REQ 133120

#define BAR_SYNC(id, cnt)   asm volatile("bar.sync %0, %1;"   :: "r"(id), "r"(cnt) : "memory")
#define BAR_ARRIVE(id, cnt) asm volatile("bar.arrive %0, %1;" :: "r"(id), "r"(cnt) : "memory")
#define MEMBAR_CTA()        asm volatile("membar.cta;" ::: "memory")

__device__ __forceinline__ uint32_t smem_u32(const void* p) {
    uint32_t a;
    asm("{ .reg .u64 t; cvta.to.shared.u64 t, %1; cvt.u32.u64 %0, t; }" : "=r"(a) : "l"(p));
    return a;
}
__device__ __forceinline__ void ldsm_x4(uint32_t* r, uint32_t addr) {
    asm volatile("ldmatrix.sync.aligned.m8n8.x4.shared.b16 {%0,%1,%2,%3}, [%4];"
                 : "=r"(r[0]), "=r"(r[1]), "=r"(r[2]), "=r"(r[3]) : "r"(addr));
}
__device__ __forceinline__ void ldsm_x4t(uint32_t* r, uint32_t addr) {
    asm volatile("ldmatrix.sync.aligned.m8n8.x4.trans.shared.b16 {%0,%1,%2,%3}, [%4];"
                 : "=r"(r[0]), "=r"(r[1]), "=r"(r[2]), "=r"(r[3]) : "r"(addr));
}
// fp16 in, fp16 accum (d packed f16x2: d[0]=row lr, d[1]=row lr+8)
__device__ __forceinline__ void mma16816h(uint32_t* d, const uint32_t* a, const uint32_t* b) {
    asm volatile("mma.sync.aligned.m16n8k16.row.col.f16.f16.f16.f16 "
                 "{%0,%1}, {%2,%3,%4,%5}, {%6,%7}, {%0,%1};"
                 : "+r"(d[0]), "+r"(d[1])
                 : "r"(a[0]), "r"(a[1]), "r"(a[2]), "r"(a[3]), "r"(b[0]), "r"(b[1]));
}
// fp16 tile address: pitch 256B/row (16 chunks of 16B = 8 cols), chunk ^= row&7
__device__ __forceinline__ uint32_t taddr(uint32_t base, int row, int col) {
    int chunk = (col >> 3) ^ (row & 7);
    return base + row * 256 + (chunk << 4);
}
__device__ __forceinline__ uint32_t h2u(__half2 v) { return *reinterpret_cast<uint32_t*>(&v); }

__global__ __launch_bounds__(512, 1)
void magnus_kernel(const float* __restrict__ t0, const float* __restrict__ hp,
                   const float* __restrict__ y0,
                   const float* __restrict__ A0, const float* __restrict__ Wm,
                   float* __restrict__ out, int B)
{
    extern __shared__ char sm[];
    const uint32_t sb = smem_u32(sm);

    const int tid  = threadIdx.x;
    const int wid  = tid >> 5;
    const int step = gridDim.x;
    const int b0   = blockIdx.x;

    const float h   = hp[0];
    const float h2  = 0.5f * h;
    const float c24 = h * h * h * (1.0f / 24.0f);

    if (wid < 8) {
        // ================= PRODUCER (warps 0-7, 256 threads) — R13 pattern =================
        const int ptid = tid;
        int i = 0;
        for (int bp = b0; bp < B; bp += step, ++i) {
            const int k = i & 1;
            if (i >= 2) BAR_SYNC(3 + k, 512);        // wait: buffer k free

            const float t0b = t0[bp];
            const float t1  = t0b + (0.5f - SQ36) * h;
            const float t2  = t0b + (0.5f + SQ36) * h;

            const float4* A0g = (const float4*)(A0 + (size_t)bp * BD);
            const float4* Wg  = (const float4*)(Wm + (size_t)bp * BD);
            float4* o1 = (float4*)(out + (size_t)B * DD + (size_t)bp * BD);
            float4* o2 = (float4*)(out + (size_t)B * DD + (size_t)B * BD + (size_t)bp * BD);

            float yv0 = 0.0f;
            if (ptid < DD) yv0 = y0[(size_t)bp * DD + ptid];   // hides behind stream

            float4 pa[2][2], pw[2][2];
            #pragma unroll
            for (int u = 0; u < 2; ++u) {
                int idx = ptid + 256 * u;
                pa[0][u] = A0g[idx];
                pw[0][u] = Wg[idx];
            }
            #pragma unroll
            for (int gp = 0; gp < 8; ++gp) {
                int cur = gp & 1;
                if (gp < 7) {
                    #pragma unroll
                    for (int u = 0; u < 2; ++u) {
                        int idx = ptid + 256 * (2 * (gp + 1) + u);
                        pa[cur ^ 1][u] = A0g[idx];
                        pw[cur ^ 1][u] = Wg[idx];
                    }
                }
                #pragma unroll
                for (int u = 0; u < 2; ++u) {
                    int idx = ptid + 256 * (2 * gp + u);
                    int row = idx >> 5;
                    int ch  = idx & 31;          // 16B fp32 chunk (4 cols)
                    float4 a = pa[cur][u];
                    float4 w = pw[cur][u];
                    float4 x1, x2;
                    x1.x = fmaf(t1, w.x, a.x); x1.y = fmaf(t1, w.y, a.y);
                    x1.z = fmaf(t1, w.z, a.z); x1.w = fmaf(t1, w.w, a.w);
                    x2.x = fmaf(t2, w.x, a.x); x2.y = fmaf(t2, w.y, a.y);
                    x2.z = fmaf(t2, w.z, a.z); x2.w = fmaf(t2, w.w, a.w);
                    o1[idx] = x1;
                    o2[idx] = x2;
                    uint2 pS, pW;
                    pS.x = h2u(__floats2half2_rn(x1.x + x2.x, x1.y + x2.y));
                    pS.y = h2u(__floats2half2_rn(x1.z + x2.z, x1.w + x2.w));
                    pW.x = h2u(__floats2half2_rn(w.x, w.y));
                    pW.y = h2u(__floats2half2_rn(w.z, w.w));
                    uint32_t toff = (uint32_t)(row * 256 + (((ch >> 1) ^ (row & 7)) << 4) + ((ch & 1) << 3));
                    *(uint2*)(sm + BUF(k) + toff)        = pS;
                    *(uint2*)(sm + BUF(k) + WOFF + toff) = pW;
                }
            }
            if (ptid < DD) *(float*)(sm + YS(k) + ptid * 4) = yv0;
            MEMBAR_CTA();
            BAR_ARRIVE(1 + k, 512);                  // signal: buffer k full
        }
    } else {
        // ================= CONSUMER (warps 8-15, 256 threads) =================
        const int ctid  = tid - 256;
        const int clane = ctid & 31;
        const int cwid  = ctid >> 5;
        float* v0 = (float*)(sm + V0OFF);
        float* v1 = (float*)(sm + V1OFF);

        const int m0 = (cwid >> 2) << 6;   // 0 or 64
        const int n0 = (cwid & 3) << 5;    // 0,32,64,96
        const int arow = clane & 15;
        const int acol = (clane >> 4) << 3;
        const int r    = ctid >> 1;
        const int half = ctid & 1;

        int i = 0;
        for (int bc = b0; bc < B; bc += step, ++i) {
            const int k = i & 1;
            BAR_SYNC(1 + k, 512);                    // wait: buffer k full
            if (ctid < DD) v0[ctid] = *(const float*)(sm + YS(k) + ctid * 4);

            const uint32_t aS = sb + BUF(k);
            const uint32_t aW = aS + WOFF;

            // ---- MMA: CM = S@W + (-W)@S (= [S,W]); 2x4 warp grid, 64x32/warp ----
            uint32_t acc[4][4][2];
            #pragma unroll
            for (int mh = 0; mh < 4; ++mh)
                #pragma unroll
                for (int nt = 0; nt < 4; ++nt) { acc[mh][nt][0] = 0u; acc[mh][nt][1] = 0u; }

            #pragma unroll
            for (int k0 = 0; k0 < DD; k0 += 16) {
                uint32_t fs[4][4], fw[4][4];
                #pragma unroll
                for (int mh = 0; mh < 4; ++mh) {
                    ldsm_x4(fs[mh], taddr(aS, m0 + 16 * mh + arow, k0 + acol));
                    ldsm_x4(fw[mh], taddr(aW, m0 + 16 * mh + arow, k0 + acol));
                    #pragma unroll
                    for (int qq = 0; qq < 4; ++qq) fw[mh][qq] ^= 0x80008000u;   // -W
                }
                #pragma unroll
                for (int nn = 0; nn < 2; ++nn) {
                    uint32_t bW[4], bS[4];
                    ldsm_x4t(bW, taddr(aW, k0 + arow, n0 + 16 * nn + acol));
                    ldsm_x4t(bS, taddr(aS, k0 + arow, n0 + 16 * nn + acol));
                    #pragma unroll
                    for (int mh = 0; mh < 4; ++mh) {
                        mma16816h(acc[mh][2 * nn],     fs[mh], bW);
                        mma16816h(acc[mh][2 * nn + 1], fs[mh], bW + 2);
                        mma16816h(acc[mh][2 * nn],     fw[mh], bS);
                        mma16816h(acc[mh][2 * nn + 1], fw[mh], bS + 2);
                    }
                }
            }
            BAR_SYNC(5, 256);    // all consumer ldsm of W tile done -> reusable

            // ---- store fp16 CM into W-tile region ----
            {
                const int lr = clane >> 2;
                const int lc = (clane & 3) << 1;
                #pragma unroll
                for (int mh = 0; mh < 4; ++mh)
                    #pragma unroll
                    for (int nt = 0; nt < 4; ++nt)
                        #pragma unroll
                        for (int hf = 0; hf < 2; ++hf) {
                            int row = m0 + 16 * mh + lr + 8 * hf;
                            int col = n0 + 8 * nt + lc;
                            uint32_t addr = (uint32_t)(row * 256 + (((col >> 3) ^ (row & 7)) << 4) + ((col & 7) << 1));
                            *(uint32_t*)(sm + BUF(k) + WOFF + addr) = acc[mh][nt][hf];
                        }
            }
            BAR_SYNC(5, 256);

            // ---- om[64] = h/2 * S - c24 * CM  (row r, half) ----
            float om[64];
            #pragma unroll
            for (int j = 0; j < 8; ++j) {
                uint32_t cc = (uint32_t)(r * 256 + ((8 * half + (j ^ (r & 7))) << 4));
                uint4 us = *(const uint4*)(sm + BUF(k) + cc);
                uint4 uc = *(const uint4*)(sm + BUF(k) + WOFF + cc);
                const uint32_t ss[4] = {us.x, us.y, us.z, us.w};
                const uint32_t cs[4] = {uc.x, uc.y, uc.z, uc.w};
                int jb = j * 8;
                #pragma unroll
                for (int t = 0; t < 4; ++t) {
                    float2 fs2 = __half22float2(*(const __half2*)&ss[t]);
                    float2 fc2 = __half22float2(*(const __half2*)&cs[t]);
                    om[jb + 2 * t + 0] = fmaf(h2, fs2.x, -c24 * fc2.x);
                    om[jb + 2 * t + 1] = fmaf(h2, fs2.y, -c24 * fc2.y);
                }
            }
            BAR_ARRIVE(3 + k, 512);                  // signal: buffer k free
            BAR_SYNC(5, 256);                        // v0 init visible to all consumers

            // ---- Taylor: y = expm(Omega) @ y0, 7 terms, shfl pair-reduce ----
            float yvreg = v0[r];
            #pragma unroll
            for (int kk = 1; kk <= 7; ++kk) {
                const float* vcur = (kk & 1) ? v0 : v1;
                float*       vnxt = (kk & 1) ? v1 : v0;
                const float4* vv = (const float4*)(vcur + 64 * half);
                float s0 = 0.f, s1 = 0.f, s2 = 0.f, s3 = 0.f;
                #pragma unroll
                for (int f4 = 0; f4 < 16; ++f4) {
                    float4 f = vv[f4];
                    s0 = fmaf(om[4 * f4 + 0], f.x, s0);
                    s1 = fmaf(om[4 * f4 + 1], f.y, s1);
                    s2 = fmaf(om[4 * f4 + 2], f.z, s2);
                    s3 = fmaf(om[4 * f4 + 3], f.w, s3);
                }
                float tot = (s0 + s1) + (s2 + s3);
                tot += __shfl_xor_sync(0xffffffffu, tot, 1);
                float nv = tot * (1.0f / (float)kk);
                yvreg += nv;
                if (half == 0) vnxt[r] = nv;
                BAR_SYNC(5, 256);
            }
            if (half == 0) out[(size_t)bc * DD + r] = yvreg;
        }
    }
}

extern "C" void kernel_launch(void* const* d_in, const int* in_sizes, int n_in,
                              void* d_out, int out_size) {
    const float* t0 = (const float*)d_in[0];
    const float* h  = (const float*)d_in[1];
    const float* y0 = (const float*)d_in[2];
    const float* A0 = (const float*)d_in[3];
    const float* W  = (const float*)d_in[4];
    const int B = in_sizes[0];

    int grid = B < 152 ? B : 152;
    cudaFuncSetAttribute(magnus_kernel, cudaFuncAttributeMaxDynamicSharedMemorySize, SMEM_REQ);
    magnus_kernel<<<grid, 512, SMEM_REQ>>>(t0, h, y0, A0, W, (float*)d_out, B);
}